// round 1
// baseline (speedup 1.0000x reference)
#include <cuda_runtime.h>
#include <math.h>

typedef unsigned long long ull;

#define T_LEN 1024
#define B_DIM 256
#define D_DIM 64
#define H_DIM 128
#define BH (B_DIM * H_DIM)          // 32768
#define R_TOT (T_LEN * B_DIM)       // 262144

// Scratch: z[t][b][j] and h_all[t][b][j]  (134 MB each)
__device__ float g_z[(size_t)T_LEN * BH];
__device__ float g_h[(size_t)T_LEN * BH];

// ---------------- packed f32x2 helpers ----------------
__device__ __forceinline__ ull pk2(float lo, float hi) {
    ull r;
    asm("mov.b64 %0, {%1,%2};" : "=l"(r) : "r"(__float_as_uint(lo)), "r"(__float_as_uint(hi)));
    return r;
}
__device__ __forceinline__ float2 upk2(ull v) {
    unsigned int lo, hi;
    asm("mov.b64 {%0,%1}, %2;" : "=r"(lo), "=r"(hi) : "l"(v));
    return make_float2(__uint_as_float(lo), __uint_as_float(hi));
}
__device__ __forceinline__ void fma2(ull& d, ull a, ull b) {
    asm("fma.rn.f32x2 %0, %1, %2, %0;" : "+l"(d) : "l"(a), "l"(b));
}

// =====================================================================
// Phase 1: z = tanh(x @ W_x^T + b_x) @ W_ih^T + b_ih      [R_TOT, 128]
// Block: 256 threads, 128 rows. Thread = 8x8 output microtile (16x16 grid).
// =====================================================================
__global__ __launch_bounds__(256) void phase1_kernel(
    const float* __restrict__ x, const float* __restrict__ W_x,
    const float* __restrict__ b_x, const float* __restrict__ W_ih,
    const float* __restrict__ b_ih)
{
    extern __shared__ float sm[];
    float* WxT  = sm;            // [64][128]   WxT[d][m] = W_x[m][d]
    float* WihT = sm + 8192;     // [128][128]  WihT[m][j] = W_ih[j][m]
    float* xs   = sm + 24576;    // [128][64]
    float* fs   = sm + 32768;    // [128][128]
    float* bxs  = sm + 49152;    // [128]
    float* bihs = sm + 49280;    // [128]

    const int tid  = threadIdx.x;
    const int row0 = blockIdx.x * 128;

    for (int i = tid; i < 64 * 128; i += 256) {
        int d = i >> 7, m = i & 127;
        WxT[i] = W_x[m * 64 + d];
    }
    for (int i = tid; i < 128 * 128; i += 256) {
        int m = i >> 7, j = i & 127;
        WihT[i] = W_ih[j * 128 + m];
    }
    if (tid < 128) { bxs[tid] = b_x[tid]; bihs[tid] = b_ih[tid]; }

    const float4* xg  = (const float4*)(x + (size_t)row0 * 64);
    float4*       xs4 = (float4*)xs;
    for (int i = tid; i < 2048; i += 256) xs4[i] = xg[i];
    __syncthreads();

    const int tx = tid & 15, ty = tid >> 4;

    // ---- GEMM1: fs = tanh(xs @ WxT + b_x) ----
    ull acc[8][4];
    #pragma unroll
    for (int i = 0; i < 8; i++)
        #pragma unroll
        for (int jp = 0; jp < 4; jp++) acc[i][jp] = 0ull;

    #pragma unroll 4
    for (int d = 0; d < 64; ++d) {
        ull a[8];
        #pragma unroll
        for (int i = 0; i < 8; i++) {
            float av = xs[(ty * 8 + i) * 64 + d];
            a[i] = pk2(av, av);
        }
        const ulonglong2* bp = (const ulonglong2*)(WxT + d * 128 + tx * 8);
        ulonglong2 b0 = bp[0], b1 = bp[1];
        #pragma unroll
        for (int i = 0; i < 8; i++) {
            fma2(acc[i][0], a[i], b0.x);
            fma2(acc[i][1], a[i], b0.y);
            fma2(acc[i][2], a[i], b1.x);
            fma2(acc[i][3], a[i], b1.y);
        }
    }
    #pragma unroll
    for (int i = 0; i < 8; i++) {
        int r = ty * 8 + i;
        #pragma unroll
        for (int jp = 0; jp < 4; jp++) {
            float2 v = upk2(acc[i][jp]);
            int c = tx * 8 + jp * 2;
            fs[r * 128 + c]     = tanhf(v.x + bxs[c]);
            fs[r * 128 + c + 1] = tanhf(v.y + bxs[c + 1]);
        }
    }
    __syncthreads();

    // ---- GEMM2: z = fs @ WihT + b_ih ----
    #pragma unroll
    for (int i = 0; i < 8; i++)
        #pragma unroll
        for (int jp = 0; jp < 4; jp++) acc[i][jp] = 0ull;

    #pragma unroll 4
    for (int m = 0; m < 128; ++m) {
        ull a[8];
        #pragma unroll
        for (int i = 0; i < 8; i++) {
            float av = fs[(ty * 8 + i) * 128 + m];
            a[i] = pk2(av, av);
        }
        const ulonglong2* bp = (const ulonglong2*)(WihT + m * 128 + tx * 8);
        ulonglong2 b0 = bp[0], b1 = bp[1];
        #pragma unroll
        for (int i = 0; i < 8; i++) {
            fma2(acc[i][0], a[i], b0.x);
            fma2(acc[i][1], a[i], b0.y);
            fma2(acc[i][2], a[i], b1.x);
            fma2(acc[i][3], a[i], b1.y);
        }
    }
    #pragma unroll
    for (int i = 0; i < 8; i++) {
        int r = row0 + ty * 8 + i;
        int c = tx * 8;
        float2 v0 = upk2(acc[i][0]), v1 = upk2(acc[i][1]);
        float2 v2 = upk2(acc[i][2]), v3 = upk2(acc[i][3]);
        float4 o0 = make_float4(v0.x + bihs[c],     v0.y + bihs[c + 1],
                                v1.x + bihs[c + 2], v1.y + bihs[c + 3]);
        float4 o1 = make_float4(v2.x + bihs[c + 4], v2.y + bihs[c + 5],
                                v3.x + bihs[c + 6], v3.y + bihs[c + 7]);
        float4* zp = (float4*)(g_z + (size_t)r * 128 + c);
        zp[0] = o0; zp[1] = o1;
    }
}

// =====================================================================
// Phase 2: recurrence. One CTA per batch row b; thread j owns output j.
// W_hh row lives in registers (64 packed f32x2). h broadcast via smem.
// =====================================================================
__global__ __launch_bounds__(128, 3) void rnn_kernel(
    const float* __restrict__ W_hh, const float* __restrict__ b_hh)
{
    __shared__ __align__(16) float hs[128];

    const int b = blockIdx.x;
    const int j = threadIdx.x;

    ull w[64];
    const ulonglong2* w2 = (const ulonglong2*)(W_hh + j * 128);
    #pragma unroll
    for (int i = 0; i < 32; i++) {
        ulonglong2 v = w2[i];
        w[2 * i]     = v.x;
        w[2 * i + 1] = v.y;
    }
    const float bh = b_hh[j];

    hs[j] = 0.0f;
    g_h[(size_t)b * 128 + j] = 0.0f;                 // h_0 = 0
    float zreg = g_z[(size_t)b * 128 + j];           // z_0
    __syncthreads();

    for (int t = 0; t < T_LEN - 1; ++t) {
        float znext = 0.0f;
        if (t < T_LEN - 2) znext = g_z[(size_t)(t + 1) * BH + b * 128 + j];

        ull a0 = 0, a1 = 0, a2 = 0, a3 = 0;
        const ulonglong2* h2 = (const ulonglong2*)hs;
        #pragma unroll
        for (int i = 0; i < 16; i++) {
            ulonglong2 hv = h2[i];
            fma2(a0, hv.x, w[2 * i]);
            fma2(a1, hv.y, w[2 * i + 1]);
        }
        #pragma unroll
        for (int i = 16; i < 32; i++) {
            ulonglong2 hv = h2[i];
            fma2(a2, hv.x, w[2 * i]);
            fma2(a3, hv.y, w[2 * i + 1]);
        }
        float2 f0 = upk2(a0), f1 = upk2(a1), f2 = upk2(a2), f3 = upk2(a3);
        float s = ((f0.x + f0.y) + (f1.x + f1.y)) + ((f2.x + f2.y) + (f3.x + f3.y));
        float hn = tanhf(s + zreg + bh);

        __syncthreads();                 // all reads of hs done
        hs[j] = hn;
        g_h[(size_t)(t + 1) * BH + b * 128 + j] = hn;
        zreg = znext;
        __syncthreads();                 // new hs visible
    }
}

// =====================================================================
// Phase 3: y = tanh(h_all @ W_h^T + b_h) @ W_g^T + b_g    [R_TOT, 64]
// In-place reuse of the h tile buffer for the tanh intermediate.
// =====================================================================
__global__ __launch_bounds__(256) void phase3_kernel(
    const float* __restrict__ W_h, const float* __restrict__ b_h,
    const float* __restrict__ W_g, const float* __restrict__ b_g,
    float* __restrict__ y)
{
    extern __shared__ float sm[];
    float* WhT = sm;             // [128][128]  WhT[m][j] = W_h[j][m]
    float* WgT = sm + 16384;     // [128][64]   WgT[j][d] = W_g[d][j]
    float* hb  = sm + 24576;     // [128][128]  h tile, reused for tanh(u)
    float* bhs = sm + 40960;     // [128]
    float* bgs = sm + 41088;     // [64]

    const int tid  = threadIdx.x;
    const int row0 = blockIdx.x * 128;

    for (int i = tid; i < 128 * 128; i += 256) {
        int m = i >> 7, j = i & 127;
        WhT[i] = W_h[j * 128 + m];
    }
    for (int i = tid; i < 128 * 64; i += 256) {
        int j = i >> 6, d = i & 63;
        WgT[i] = W_g[d * 128 + j];
    }
    if (tid < 128) bhs[tid] = b_h[tid];
    if (tid < 64)  bgs[tid] = b_g[tid];

    const float4* hg  = (const float4*)(g_h + (size_t)row0 * 128);
    float4*       hb4 = (float4*)hb;
    for (int i = tid; i < 4096; i += 256) hb4[i] = hg[i];
    __syncthreads();

    const int tx = tid & 15, ty = tid >> 4;

    // ---- GEMM1: u = tanh(hb @ WhT + b_h) ----
    ull acc[8][4];
    #pragma unroll
    for (int i = 0; i < 8; i++)
        #pragma unroll
        for (int jp = 0; jp < 4; jp++) acc[i][jp] = 0ull;

    #pragma unroll 4
    for (int m = 0; m < 128; ++m) {
        ull a[8];
        #pragma unroll
        for (int i = 0; i < 8; i++) {
            float av = hb[(ty * 8 + i) * 128 + m];
            a[i] = pk2(av, av);
        }
        const ulonglong2* bp = (const ulonglong2*)(WhT + m * 128 + tx * 8);
        ulonglong2 b0 = bp[0], b1 = bp[1];
        #pragma unroll
        for (int i = 0; i < 8; i++) {
            fma2(acc[i][0], a[i], b0.x);
            fma2(acc[i][1], a[i], b0.y);
            fma2(acc[i][2], a[i], b1.x);
            fma2(acc[i][3], a[i], b1.y);
        }
    }
    __syncthreads();   // all reads of hb done before in-place overwrite
    #pragma unroll
    for (int i = 0; i < 8; i++) {
        int r = ty * 8 + i;
        #pragma unroll
        for (int jp = 0; jp < 4; jp++) {
            float2 v = upk2(acc[i][jp]);
            int c = tx * 8 + jp * 2;
            hb[r * 128 + c]     = tanhf(v.x + bhs[c]);
            hb[r * 128 + c + 1] = tanhf(v.y + bhs[c + 1]);
        }
    }
    __syncthreads();

    // ---- GEMM2: y = u @ WgT + b_g  (64 output cols -> 8x4 microtile) ----
    ull ac2[8][2];
    #pragma unroll
    for (int i = 0; i < 8; i++) { ac2[i][0] = 0ull; ac2[i][1] = 0ull; }

    #pragma unroll 4
    for (int m = 0; m < 128; ++m) {
        ull a[8];
        #pragma unroll
        for (int i = 0; i < 8; i++) {
            float av = hb[(ty * 8 + i) * 128 + m];
            a[i] = pk2(av, av);
        }
        const ulonglong2* bp = (const ulonglong2*)(WgT + m * 64 + tx * 4);
        ulonglong2 bv = bp[0];
        #pragma unroll
        for (int i = 0; i < 8; i++) {
            fma2(ac2[i][0], a[i], bv.x);
            fma2(ac2[i][1], a[i], bv.y);
        }
    }
    #pragma unroll
    for (int i = 0; i < 8; i++) {
        int r = row0 + ty * 8 + i;
        int c = tx * 4;
        float2 v0 = upk2(ac2[i][0]), v1 = upk2(ac2[i][1]);
        float4 o = make_float4(v0.x + bgs[c],     v0.y + bgs[c + 1],
                               v1.x + bgs[c + 2], v1.y + bgs[c + 3]);
        ((float4*)(y + (size_t)r * 64 + c))[0] = o;
    }
}

// =====================================================================
extern "C" void kernel_launch(void* const* d_in, const int* in_sizes, int n_in,
                              void* d_out, int out_size)
{
    const float* x    = (const float*)d_in[0];
    const float* W_x  = (const float*)d_in[1];
    const float* b_x  = (const float*)d_in[2];
    const float* W_ih = (const float*)d_in[3];
    const float* b_ih = (const float*)d_in[4];
    const float* W_hh = (const float*)d_in[5];
    const float* b_hh = (const float*)d_in[6];
    const float* W_h  = (const float*)d_in[7];
    const float* b_h  = (const float*)d_in[8];
    const float* W_g  = (const float*)d_in[9];
    const float* b_g  = (const float*)d_in[10];
    float* y = (float*)d_out;

    // Idempotent; executes outside stream semantics, attribute persists from
    // the (uncaptured) correctness call onward.
    cudaFuncSetAttribute(phase1_kernel, cudaFuncAttributeMaxDynamicSharedMemorySize, 49408 * 4);
    cudaFuncSetAttribute(phase3_kernel, cudaFuncAttributeMaxDynamicSharedMemorySize, 41152 * 4);

    phase1_kernel<<<R_TOT / 128, 256, 49408 * 4>>>(x, W_x, b_x, W_ih, b_ih);
    rnn_kernel<<<B_DIM, 128>>>(W_hh, b_hh);
    phase3_kernel<<<R_TOT / 128, 256, 41152 * 4>>>(W_h, b_h, W_g, b_g, y);
}